// round 4
// baseline (speedup 1.0000x reference)
#include <cuda_runtime.h>

#define NB      128     // persistent CTAs (< 148 SMs -> co-resident, barrier safe)
#define THREADS 512     // 16 warps, 4 per SMSP
#define BB      64      // batch
#define SS      2048    // seq len
#define HH      512     // hidden
#define VV      25      // vocab

// h double buffer (non-duplicated): [parity][k][batch-slot]
__device__ float g_h[2][HH * BB];
__device__ unsigned g_count;

__global__ void init_barrier_kernel() { g_count = 0u; }

// packed fp32x2 FMA (Blackwell): acc += x * y elementwise on 2 lanes
__device__ __forceinline__ void ffma2(float2& a, const float2 x, const float2 y) {
    asm("fma.rn.f32x2 %0, %1, %2, %0;"
        : "+l"(reinterpret_cast<unsigned long long&>(a))
        : "l"(reinterpret_cast<const unsigned long long&>(x)),
          "l"(reinterpret_cast<const unsigned long long&>(y)));
}

// fast, saturation-safe sigmoid / tanh
__device__ __forceinline__ float sigm(float x) {
    float e = __expf(-x);
    return __fdividef(1.f, 1.f + e);
}
__device__ __forceinline__ float tanha(float x) {
    return fmaf(2.f, sigm(2.f * x), -1.f);
}

// grid barrier: REDG release arrive + direct acquire-poll of one counter
__device__ __forceinline__ void grid_barrier(int tid, unsigned barno) {
    __syncthreads();
    if (tid == 0) {
        asm volatile("red.release.gpu.global.add.u32 [%0], 1;"
                     :: "l"(&g_count) : "memory");
        unsigned v;
        do {
            asm volatile("ld.acquire.gpu.global.u32 %0, [%1];"
                         : "=r"(v) : "l"(&g_count));
        } while (v < barno * (unsigned)NB);
    }
    __syncthreads();
}

// dynamic smem layout (floats)
#define WSP_FLOATS  (HH * 16)          // [p][16]: 8 row-pairs {w_r0,w_r1}, dense 64B/k
#define WXB_FLOATS  (16 * 32)          // [r][vocab padded 32], biases folded
#define GRD_FLOATS  (2 * BB * 20)      // [kh][batch][20]: 16 gate rows + pad
#define SMEM_BYTES  ((WSP_FLOATS + WXB_FLOATS + GRD_FLOATS + 3 * BB) * 4)

__global__ void __launch_bounds__(THREADS, 1) lstm_persistent_kernel(
    const int* __restrict__ tokens, const int* __restrict__ lengths,
    const float* __restrict__ W_ih, const float* __restrict__ W_hh,
    const float* __restrict__ b_ih, const float* __restrict__ b_hh,
    const float* __restrict__ fc_w, const float* __restrict__ fc_b,
    float* __restrict__ out)
{
    extern __shared__ char smem_raw[];
    float* wsp   = reinterpret_cast<float*>(smem_raw);
    float* wxb   = wsp + WSP_FLOATS;
    float* gredp = wxb + WXB_FLOATS;              // [kh*64*20 + b*20 + r]
    int*   slen   = reinterpret_cast<int*>(gredp + GRD_FLOATS);
    int*   sorder = slen + BB;
    int*   lens   = sorder + BB;

    const int tid = threadIdx.x;
    const int c4  = blockIdx.x * 4;   // this CTA's 4 hidden dims

    // ---- W_hh chunk into smem, permuted + row-pair packed ----
    // real k = kh*256 + kq*32 + i  ->  stored at p = kh*256 + i*8 + kq
    // wsp[p*16 + r], r = gate*4 + j (16 rows for this CTA)
    for (int idx = tid; idx < 16 * HH; idx += THREADS) {
        int r = idx >> 9, k = idx & (HH - 1);      // k fast -> coalesced gmem read
        int kh = k >> 8, kq = (k >> 5) & 7, i = k & 31;
        int p = kh * 256 + i * 8 + kq;
        int R = (r >> 2) * HH + c4 + (r & 3);
        wsp[p * 16 + r] = W_hh[R * HH + k];
    }
    // ---- W_ih folded with biases ----
    for (int idx = tid; idx < 16 * VV; idx += THREADS) {
        int r = idx / VV, v = idx - r * VV;
        int R = (r >> 2) * HH + c4 + (r & 3);
        wxb[r * 32 + v] = W_ih[R * VV + v] + b_ih[R] + b_hh[R];
    }
    // ---- stable descending argsort of lengths ----
    if (tid < BB) lens[tid] = lengths[tid];
    __syncthreads();
    if (tid < BB) {
        int L = lens[tid], rk = 0;
        for (int b2 = 0; b2 < BB; b2++) {
            int L2 = lens[b2];
            rk += (L2 > L) || (L2 == L && b2 < tid);
        }
        sorder[rk] = tid;
        slen[rk]   = L;
    }
    // ---- zero this CTA's rows of h buffer 0 ----
    for (int idx = tid; idx < 4 * BB; idx += THREADS) {
        g_h[0][(c4 + (idx >> 6)) * BB + (idx & 63)] = 0.f;
    }
    __syncthreads();
    const int T = slen[0];

    // per-warp step-invariant setup
    const int w = tid >> 5, lane = tid & 31;
    const int g = w >> 1, kh = w & 1;             // batch group (8 batches), k half
    const int kq = lane >> 2, bp = lane & 3;      // 8-way k split, batch pair in group
    const int glen = slen[8 * g];                 // group max length

    // activation mapping (kh==0 warps only): lane -> (j, b)
    const int aj = lane >> 3, ab = lane & 7;
    const int sb = 8 * g + ab;                    // batch slot
    const int alen = slen[sb];
    const int* tokrow = tokens + sorder[sb] * SS;
    float creg = 0.f;                             // private cell state (kh==0 lanes)

    unsigned barno = 1;
    grid_barrier(tid, barno);

    for (int t = 0; t < T; t++) {
        const float* hr = g_h[t & 1];
        float*       hw = g_h[(t & 1) ^ 1];

        // early token fetch
        int tok = 0;
        if (kh == 0 && t < alen) tok = __ldg(tokrow + t);

        // ---- recurrent matmul: warp pair = (8 batches) x (16 rows) x (512 k) ----
        if (t < glen) {
            // lane k at iter i: kh*256 + kq*32 + i; h col = 8g + 2bp (float2)
            const float2* hp = reinterpret_cast<const float2*>(
                hr + (kh * 256 + kq * 32) * BB) + (4 * g + bp);
            // W at permuted p = kh*256 + i*8 + kq, float4 units
            const float4* wp = reinterpret_cast<const float4*>(wsp)
                               + (kh * 256 + kq) * 4;
            float2 acc[8][2];   // acc[q][b2] = rows {2q,2q+1} for batch (8g+2bp+b2)
#pragma unroll
            for (int q = 0; q < 8; q++) { acc[q][0] = make_float2(0.f, 0.f);
                                          acc[q][1] = make_float2(0.f, 0.f); }
#pragma unroll 4
            for (int i = 0; i < 32; i++) {
                float2 h2 = __ldcg(hp); hp += 32;                 // next k (stride 64 fl)
                float4 w0 = wp[0], w1 = wp[1], w2 = wp[2], w3 = wp[3];
                wp += 32;                                         // next p-block (8 k)
                float2 ha = make_float2(h2.x, h2.x);
                float2 hb = make_float2(h2.y, h2.y);
                ffma2(acc[0][0], make_float2(w0.x, w0.y), ha);
                ffma2(acc[0][1], make_float2(w0.x, w0.y), hb);
                ffma2(acc[1][0], make_float2(w0.z, w0.w), ha);
                ffma2(acc[1][1], make_float2(w0.z, w0.w), hb);
                ffma2(acc[2][0], make_float2(w1.x, w1.y), ha);
                ffma2(acc[2][1], make_float2(w1.x, w1.y), hb);
                ffma2(acc[3][0], make_float2(w1.z, w1.w), ha);
                ffma2(acc[3][1], make_float2(w1.z, w1.w), hb);
                ffma2(acc[4][0], make_float2(w2.x, w2.y), ha);
                ffma2(acc[4][1], make_float2(w2.x, w2.y), hb);
                ffma2(acc[5][0], make_float2(w2.z, w2.w), ha);
                ffma2(acc[5][1], make_float2(w2.z, w2.w), hb);
                ffma2(acc[6][0], make_float2(w3.x, w3.y), ha);
                ffma2(acc[6][1], make_float2(w3.x, w3.y), hb);
                ffma2(acc[7][0], make_float2(w3.z, w3.w), ha);
                ffma2(acc[7][1], make_float2(w3.z, w3.w), hb);
            }
            // reduce over kq (lane bits 2..4)
#pragma unroll
            for (int m = 4; m <= 16; m <<= 1) {
#pragma unroll
                for (int q = 0; q < 8; q++) {
                    acc[q][0].x += __shfl_xor_sync(0xffffffffu, acc[q][0].x, m);
                    acc[q][0].y += __shfl_xor_sync(0xffffffffu, acc[q][0].y, m);
                    acc[q][1].x += __shfl_xor_sync(0xffffffffu, acc[q][1].x, m);
                    acc[q][1].y += __shfl_xor_sync(0xffffffffu, acc[q][1].y, m);
                }
            }
            if (lane < 4) {  // bp lanes hold sums for batches 8g+2bp, 8g+2bp+1
                float4* gp = reinterpret_cast<float4*>(
                    gredp + kh * (BB * 20) + (8 * g + 2 * bp) * 20);
                gp[0] = make_float4(acc[0][0].x, acc[0][0].y, acc[1][0].x, acc[1][0].y);
                gp[1] = make_float4(acc[2][0].x, acc[2][0].y, acc[3][0].x, acc[3][0].y);
                gp[2] = make_float4(acc[4][0].x, acc[4][0].y, acc[5][0].x, acc[5][0].y);
                gp[3] = make_float4(acc[6][0].x, acc[6][0].y, acc[7][0].x, acc[7][0].y);
                float4* gq = reinterpret_cast<float4*>(
                    gredp + kh * (BB * 20) + (8 * g + 2 * bp + 1) * 20);
                gq[0] = make_float4(acc[0][1].x, acc[0][1].y, acc[1][1].x, acc[1][1].y);
                gq[1] = make_float4(acc[2][1].x, acc[2][1].y, acc[3][1].x, acc[3][1].y);
                gq[2] = make_float4(acc[4][1].x, acc[4][1].y, acc[5][1].x, acc[5][1].y);
                gq[3] = make_float4(acc[6][1].x, acc[6][1].y, acc[7][1].x, acc[7][1].y);
            }
            // pair sync: both k-half warps' partials visible (named barrier, 64 thr)
            asm volatile("bar.sync %0, 64;" :: "r"(g + 1) : "memory");
        }

        // ---- activation + state update: kh==0 warp, lane = (j, b) ----
        if (kh == 0 && t <= glen) {
            float* hwp = hw + (c4 + aj) * BB + sb;
            if (t < alen) {
                const float* g0 = gredp + sb * 20;
                const float* g1 = gredp + BB * 20 + sb * 20;
                float gi = g0[aj]      + g1[aj]      + wxb[(aj)      * 32 + tok];
                float gf = g0[4 + aj]  + g1[4 + aj]  + wxb[(4 + aj)  * 32 + tok];
                float gg = g0[8 + aj]  + g1[8 + aj]  + wxb[(8 + aj)  * 32 + tok];
                float go = g0[12 + aj] + g1[12 + aj] + wxb[(12 + aj) * 32 + tok];
                float cn = sigm(gf) * creg + sigm(gi) * tanha(gg);
                creg = cn;
                __stcg(hwp, sigm(go) * tanha(cn));
            } else if (t == alen) {
                // first frozen step: mirror final h into the other parity buffer
                __stcg(hwp, __ldcg(hr + (c4 + aj) * BB + sb));
            }
        }

        barno++;
        grid_barrier(tid, barno);
    }

    // ---- final FC: out[s] = fc_w . h_final[:, s] + fc_b (sorted order) ----
    if (blockIdx.x == 0 && tid < 256) {
        const float* hf = g_h[T & 1];
        int s = tid >> 2, q = tid & 3;
        float p = 0.f;
        for (int kk = 0; kk < 128; kk++) {
            int k = q * 128 + kk;
            p += __ldcg(&hf[k * BB + s]) * __ldg(&fc_w[k]);
        }
        p += __shfl_down_sync(0xffffffffu, p, 1);
        p += __shfl_down_sync(0xffffffffu, p, 2);
        if (q == 0) out[s] = p + __ldg(fc_b);
    }
}

extern "C" void kernel_launch(void* const* d_in, const int* in_sizes, int n_in,
                              void* d_out, int out_size) {
    const int*   tokens  = (const int*)d_in[0];
    const int*   lengths = (const int*)d_in[1];
    const float* W_ih    = (const float*)d_in[2];
    const float* W_hh    = (const float*)d_in[3];
    const float* b_ih    = (const float*)d_in[4];
    const float* b_hh    = (const float*)d_in[5];
    const float* fc_w    = (const float*)d_in[6];
    const float* fc_b    = (const float*)d_in[7];
    float* out = (float*)d_out;

    cudaFuncSetAttribute(lstm_persistent_kernel,
                         cudaFuncAttributeMaxDynamicSharedMemorySize, SMEM_BYTES);
    init_barrier_kernel<<<1, 1>>>();
    lstm_persistent_kernel<<<NB, THREADS, SMEM_BYTES>>>(
        tokens, lengths, W_ih, W_hh, b_ih, b_hh, fc_w, fc_b, out);
}

// round 5
// speedup vs baseline: 1.1893x; 1.1893x over previous
#include <cuda_runtime.h>

#define NB      128     // persistent CTAs (< 148 SMs -> co-resident, barrier safe)
#define THREADS 512     // 16 warps, 4 per SMSP
#define BB      64      // batch
#define SS      2048    // seq len
#define HH      512     // hidden
#define VV      25      // vocab

// h double buffer (non-duplicated): [parity][k][batch-slot]
__device__ float g_h[2][HH * BB];
__device__ unsigned g_count;

__global__ void init_barrier_kernel() { g_count = 0u; }

// packed fp32x2 FMA (Blackwell): acc += x * y elementwise on 2 lanes
__device__ __forceinline__ void ffma2(float2& a, const float2 x, const float2 y) {
    asm("fma.rn.f32x2 %0, %1, %2, %0;"
        : "+l"(reinterpret_cast<unsigned long long&>(a))
        : "l"(reinterpret_cast<const unsigned long long&>(x)),
          "l"(reinterpret_cast<const unsigned long long&>(y)));
}

// fast, saturation-safe sigmoid / tanh
__device__ __forceinline__ float sigm(float x) {
    float e = __expf(-x);
    return __fdividef(1.f, 1.f + e);
}
__device__ __forceinline__ float tanha(float x) {
    return fmaf(2.f, sigm(2.f * x), -1.f);
}

// grid barrier: REDG release arrive + direct acquire-poll of one counter
__device__ __forceinline__ void grid_barrier(int tid, unsigned barno) {
    __syncthreads();
    if (tid == 0) {
        asm volatile("red.release.gpu.global.add.u32 [%0], 1;"
                     :: "l"(&g_count) : "memory");
        unsigned v;
        do {
            asm volatile("ld.acquire.gpu.global.u32 %0, [%1];"
                         : "=r"(v) : "l"(&g_count));
        } while (v < barno * (unsigned)NB);
    }
    __syncthreads();
}

// dynamic smem layout (floats)
#define WSP_FLOATS  (HH * 20)          // [k][20]: 16 rows (r=gate*4+j) + 4 pad (CONFLICT-FREE)
#define WXB_FLOATS  (16 * 32)          // [r][vocab padded 32], biases folded
#define GRD_FLOATS  (2 * BB * 20)      // [kh][batch][20]: 16 gate rows + pad
#define SMEM_BYTES  ((WSP_FLOATS + WXB_FLOATS + GRD_FLOATS + 3 * BB) * 4)

__global__ void __launch_bounds__(THREADS, 1) lstm_persistent_kernel(
    const int* __restrict__ tokens, const int* __restrict__ lengths,
    const float* __restrict__ W_ih, const float* __restrict__ W_hh,
    const float* __restrict__ b_ih, const float* __restrict__ b_hh,
    const float* __restrict__ fc_w, const float* __restrict__ fc_b,
    float* __restrict__ out)
{
    extern __shared__ char smem_raw[];
    float* wsp   = reinterpret_cast<float*>(smem_raw);
    float* wxb   = wsp + WSP_FLOATS;
    float* gredp = wxb + WXB_FLOATS;              // [kh*64*20 + b*20 + r]
    int*   slen   = reinterpret_cast<int*>(gredp + GRD_FLOATS);
    int*   sorder = slen + BB;
    int*   lens   = sorder + BB;

    const int tid = threadIdx.x;
    const int c4  = blockIdx.x * 4;   // this CTA's 4 hidden dims

    // ---- W_hh chunk into smem: wsp[k*20 + r], r = gate*4 + j ----
    for (int idx = tid; idx < 16 * HH; idx += THREADS) {
        int r = idx >> 9, k = idx & (HH - 1);
        int R = (r >> 2) * HH + c4 + (r & 3);
        wsp[k * 20 + r] = W_hh[R * HH + k];
    }
    // ---- W_ih folded with biases ----
    for (int idx = tid; idx < 16 * VV; idx += THREADS) {
        int r = idx / VV, v = idx - r * VV;
        int R = (r >> 2) * HH + c4 + (r & 3);
        wxb[r * 32 + v] = W_ih[R * VV + v] + b_ih[R] + b_hh[R];
    }
    // ---- stable descending argsort of lengths ----
    if (tid < BB) lens[tid] = lengths[tid];
    __syncthreads();
    if (tid < BB) {
        int L = lens[tid], rk = 0;
        for (int b2 = 0; b2 < BB; b2++) {
            int L2 = lens[b2];
            rk += (L2 > L) || (L2 == L && b2 < tid);
        }
        sorder[rk] = tid;
        slen[rk]   = L;
    }
    // ---- zero this CTA's rows of h buffer 0 ----
    for (int idx = tid; idx < 4 * BB; idx += THREADS) {
        g_h[0][(c4 + (idx >> 6)) * BB + (idx & 63)] = 0.f;
    }
    __syncthreads();
    const int T = slen[0];

    // per-warp step-invariant setup
    const int w = tid >> 5, lane = tid & 31;
    const int g = w >> 1, kh = w & 1;             // batch group (8 batches), k half
    const int kq = lane >> 2, bp = lane & 3;      // 8-way k split, batch pair in group
    const int glen = slen[8 * g];                 // group max length
    const int kstart = kh * 256 + kq;             // lane's k: kstart + 8*i, i<32

    // activation mapping (kh==0 warps only): lane -> (j, b)
    const int aj = lane >> 3, ab = lane & 7;
    const int sb = 8 * g + ab;                    // batch slot
    const int alen = slen[sb];
    const int* tokrow = tokens + sorder[sb] * SS;
    float creg = 0.f;                             // private cell state (kh==0 lanes)

    unsigned barno = 1;
    grid_barrier(tid, barno);

    for (int t = 0; t < T; t++) {
        const float* hr = g_h[t & 1];
        float*       hw = g_h[(t & 1) ^ 1];

        // early token fetch
        int tok = 0;
        if (kh == 0 && t < alen) tok = __ldg(tokrow + t);

        // ---- recurrent matmul: warp pair = (8 batches) x (16 rows) x (512 k) ----
        if (t < glen) {
            // lane k at block j, iter i: kstart + 8*(4*blk + j)
            // h float2 element index: k*32 + (4g + bp)  (stride per k-step-of-8: 256)
            const float2* hp = reinterpret_cast<const float2*>(hr)
                               + (kstart * 32 + 4 * g + bp);
            const float4* wp = reinterpret_cast<const float4*>(wsp) + kstart * 5;
            float2 acc[8][2];   // acc[q][b2] = rows {2q,2q+1} for batch (8g+2bp+b2)
#pragma unroll
            for (int q = 0; q < 8; q++) { acc[q][0] = make_float2(0.f, 0.f);
                                          acc[q][1] = make_float2(0.f, 0.f); }
            // software pipeline: 8 blocks of 4 k-steps, h prefetch one block ahead
            float2 hbuf[4];
#pragma unroll
            for (int j = 0; j < 4; j++) hbuf[j] = __ldcg(hp + j * 256);
            hp += 4 * 256;
#pragma unroll 2
            for (int blk = 0; blk < 8; blk++) {
                float2 hcur[4];
#pragma unroll
                for (int j = 0; j < 4; j++) hcur[j] = hbuf[j];
                if (blk < 7) {
#pragma unroll
                    for (int j = 0; j < 4; j++) hbuf[j] = __ldcg(hp + j * 256);
                    hp += 4 * 256;
                }
#pragma unroll
                for (int j = 0; j < 4; j++) {
                    float4 w0 = wp[0], w1 = wp[1], w2 = wp[2], w3 = wp[3];
                    wp += 8 * 5;
                    float2 ha = make_float2(hcur[j].x, hcur[j].x);
                    float2 hb = make_float2(hcur[j].y, hcur[j].y);
                    ffma2(acc[0][0], make_float2(w0.x, w0.y), ha);
                    ffma2(acc[0][1], make_float2(w0.x, w0.y), hb);
                    ffma2(acc[1][0], make_float2(w0.z, w0.w), ha);
                    ffma2(acc[1][1], make_float2(w0.z, w0.w), hb);
                    ffma2(acc[2][0], make_float2(w1.x, w1.y), ha);
                    ffma2(acc[2][1], make_float2(w1.x, w1.y), hb);
                    ffma2(acc[3][0], make_float2(w1.z, w1.w), ha);
                    ffma2(acc[3][1], make_float2(w1.z, w1.w), hb);
                    ffma2(acc[4][0], make_float2(w2.x, w2.y), ha);
                    ffma2(acc[4][1], make_float2(w2.x, w2.y), hb);
                    ffma2(acc[5][0], make_float2(w2.z, w2.w), ha);
                    ffma2(acc[5][1], make_float2(w2.z, w2.w), hb);
                    ffma2(acc[6][0], make_float2(w3.x, w3.y), ha);
                    ffma2(acc[6][1], make_float2(w3.x, w3.y), hb);
                    ffma2(acc[7][0], make_float2(w3.z, w3.w), ha);
                    ffma2(acc[7][1], make_float2(w3.z, w3.w), hb);
                }
            }
            // reduce over kq (lane bits 2..4)
#pragma unroll
            for (int m = 4; m <= 16; m <<= 1) {
#pragma unroll
                for (int q = 0; q < 8; q++) {
                    acc[q][0].x += __shfl_xor_sync(0xffffffffu, acc[q][0].x, m);
                    acc[q][0].y += __shfl_xor_sync(0xffffffffu, acc[q][0].y, m);
                    acc[q][1].x += __shfl_xor_sync(0xffffffffu, acc[q][1].x, m);
                    acc[q][1].y += __shfl_xor_sync(0xffffffffu, acc[q][1].y, m);
                }
            }
            if (lane < 4) {  // bp lanes hold sums for batches 8g+2bp, 8g+2bp+1
                float4* gp = reinterpret_cast<float4*>(
                    gredp + kh * (BB * 20) + (8 * g + 2 * bp) * 20);
                gp[0] = make_float4(acc[0][0].x, acc[0][0].y, acc[1][0].x, acc[1][0].y);
                gp[1] = make_float4(acc[2][0].x, acc[2][0].y, acc[3][0].x, acc[3][0].y);
                gp[2] = make_float4(acc[4][0].x, acc[4][0].y, acc[5][0].x, acc[5][0].y);
                gp[3] = make_float4(acc[6][0].x, acc[6][0].y, acc[7][0].x, acc[7][0].y);
                float4* gq = reinterpret_cast<float4*>(
                    gredp + kh * (BB * 20) + (8 * g + 2 * bp + 1) * 20);
                gq[0] = make_float4(acc[0][1].x, acc[0][1].y, acc[1][1].x, acc[1][1].y);
                gq[1] = make_float4(acc[2][1].x, acc[2][1].y, acc[3][1].x, acc[3][1].y);
                gq[2] = make_float4(acc[4][1].x, acc[4][1].y, acc[5][1].x, acc[5][1].y);
                gq[3] = make_float4(acc[6][1].x, acc[6][1].y, acc[7][1].x, acc[7][1].y);
            }
            // pair sync: both k-half warps' partials visible (named barrier, 64 thr)
            asm volatile("bar.sync %0, 64;" :: "r"(g + 1) : "memory");
        }

        // ---- activation + state update: kh==0 warp, lane = (j, b) ----
        if (kh == 0 && t <= glen) {
            float* hwp = hw + (c4 + aj) * BB + sb;
            if (t < alen) {
                const float* g0 = gredp + sb * 20;
                const float* g1 = gredp + BB * 20 + sb * 20;
                float gi = g0[aj]      + g1[aj]      + wxb[(aj)      * 32 + tok];
                float gf = g0[4 + aj]  + g1[4 + aj]  + wxb[(4 + aj)  * 32 + tok];
                float gg = g0[8 + aj]  + g1[8 + aj]  + wxb[(8 + aj)  * 32 + tok];
                float go = g0[12 + aj] + g1[12 + aj] + wxb[(12 + aj) * 32 + tok];
                float cn = sigm(gf) * creg + sigm(gi) * tanha(gg);
                creg = cn;
                __stcg(hwp, sigm(go) * tanha(cn));
            } else if (t == alen) {
                // first frozen step: mirror final h into the other parity buffer
                __stcg(hwp, __ldcg(hr + (c4 + aj) * BB + sb));
            }
        }

        barno++;
        grid_barrier(tid, barno);
    }

    // ---- final FC: out[s] = fc_w . h_final[:, s] + fc_b (sorted order) ----
    if (blockIdx.x == 0 && tid < 256) {
        const float* hf = g_h[T & 1];
        int s = tid >> 2, q = tid & 3;
        float p = 0.f;
        for (int kk = 0; kk < 128; kk++) {
            int k = q * 128 + kk;
            p += __ldcg(&hf[k * BB + s]) * __ldg(&fc_w[k]);
        }
        p += __shfl_down_sync(0xffffffffu, p, 1);
        p += __shfl_down_sync(0xffffffffu, p, 2);
        if (q == 0) out[s] = p + __ldg(fc_b);
    }
}

extern "C" void kernel_launch(void* const* d_in, const int* in_sizes, int n_in,
                              void* d_out, int out_size) {
    const int*   tokens  = (const int*)d_in[0];
    const int*   lengths = (const int*)d_in[1];
    const float* W_ih    = (const float*)d_in[2];
    const float* W_hh    = (const float*)d_in[3];
    const float* b_ih    = (const float*)d_in[4];
    const float* b_hh    = (const float*)d_in[5];
    const float* fc_w    = (const float*)d_in[6];
    const float* fc_b    = (const float*)d_in[7];
    float* out = (float*)d_out;

    cudaFuncSetAttribute(lstm_persistent_kernel,
                         cudaFuncAttributeMaxDynamicSharedMemorySize, SMEM_BYTES);
    init_barrier_kernel<<<1, 1>>>();
    lstm_persistent_kernel<<<NB, THREADS, SMEM_BYTES>>>(
        tokens, lengths, W_ih, W_hh, b_ih, b_hh, fc_w, fc_b, out);
}